// round 14
// baseline (speedup 1.0000x reference)
#include <cuda_runtime.h>
#include <cuda_bf16.h>
#include <cstdint>

#define PBY 80      // staged row pitch bytes (40 bf16)

// smem offsets (bytes)
#define O_WQ 0            // 128 f
#define O_WK 512          // 128 f
#define O_AL 1024         // 64 f
#define O_M 1280          // 64 f
#define O_INV 1536        // 64 f
#define O_RED 1792        // 1024 f = 4096 B -> 5888
#define O_AH 6144         // 2 x 128x80 = 20480
#define O_ALO 26624       // 2 x 10240
#define O_BH 47104        // 64 x 80 = 5120
#define O_BL 52224        // 5120
#define O_RAW 57344       // 2 x 8192 raw f32 B chunks
#define SMEM_BYTES 73728

// Pre-split weights (bf16 hi/lo) in the exact smem row image (cp.async-able).
__device__ __align__(16) uint2 g_wk_hi[4][128][8];
__device__ __align__(16) uint2 g_wk_lo[4][128][8];
__device__ __align__(16) uint2 g_wv_hi[4][128][8];

__device__ __forceinline__ uint32_t smem_u32(const void* p) {
    uint32_t a;
    asm("{ .reg .u64 t; cvta.to.shared.u64 t, %1; cvt.u32.u64 %0, t; }"
        : "=r"(a) : "l"(p));
    return a;
}
__device__ __forceinline__ float bf16rt(float x) {
    return __bfloat162float(__float2bfloat16(x));
}
__device__ __forceinline__ uint32_t bf16pair(float lo, float hi) {
    __nv_bfloat162 t = __floats2bfloat162_rn(lo, hi);
    return *(uint32_t*)&t;
}
__device__ __forceinline__ void split4(float4 v, uint2& h, uint2& l) {
    h.x = bf16pair(v.x, v.y);
    h.y = bf16pair(v.z, v.w);
    l.x = bf16pair(v.x - bf16rt(v.x), v.y - bf16rt(v.y));
    l.y = bf16pair(v.z - bf16rt(v.z), v.w - bf16rt(v.w));
}
__device__ __forceinline__ void ldsm4(uint32_t* r, uint32_t addr) {
    asm volatile("ldmatrix.sync.aligned.m8n8.x4.shared.b16 {%0,%1,%2,%3}, [%4];"
                 : "=r"(r[0]), "=r"(r[1]), "=r"(r[2]), "=r"(r[3]) : "r"(addr));
}
__device__ __forceinline__ void mma16(float* d, const uint32_t* a, const uint32_t* b) {
    asm volatile(
        "mma.sync.aligned.m16n8k16.row.col.f32.bf16.bf16.f32 "
        "{%0,%1,%2,%3}, {%4,%5,%6,%7}, {%8,%9}, {%0,%1,%2,%3};"
        : "+f"(d[0]), "+f"(d[1]), "+f"(d[2]), "+f"(d[3])
        : "r"(a[0]), "r"(a[1]), "r"(a[2]), "r"(a[3]), "r"(b[0]), "r"(b[1]));
}
__device__ __forceinline__ void mma8x(float acc[2][4][4], const uint32_t* a0,
                                      const uint32_t* a1, const uint32_t* b0,
                                      const uint32_t* b1) {
    mma16(acc[0][0], a0, b0);
    mma16(acc[0][1], a0, b0 + 2);
    mma16(acc[0][2], a0, b1);
    mma16(acc[0][3], a0, b1 + 2);
    mma16(acc[1][0], a1, b0);
    mma16(acc[1][1], a1, b0 + 2);
    mma16(acc[1][2], a1, b1);
    mma16(acc[1][3], a1, b1 + 2);
}
__device__ __forceinline__ void cp16(uint32_t dst, const float* src) {
    asm volatile("cp.async.cg.shared.global [%0], [%1], 16;"
                 :: "r"(dst), "l"(__cvta_generic_to_global(src)) : "memory");
}
#define CP_COMMIT() asm volatile("cp.async.commit_group;" ::: "memory")
#define CP_WAIT(n) asm volatile("cp.async.wait_group %0;" :: "n"(n) : "memory")

// ---------------- prep: split Wk (hi+lo) and Wv (hi) once ----------------
__global__ void prep_kernel(const float* __restrict__ Wk,
                            const float* __restrict__ Wv) {
    const int c = blockIdx.x;
    const int j = threadIdx.x >> 2, kq = threadIdx.x & 3;
    const int kc = c * 32;
    uint2 h, l;
    float4 a = __ldg((const float4*)(Wk + j * 128 + kc) + kq);
    float4 b = __ldg((const float4*)(Wk + j * 128 + kc) + kq + 4);
    split4(a, h, l);
    g_wk_hi[c][j][kq] = h;
    g_wk_lo[c][j][kq] = l;
    split4(b, h, l);
    g_wk_hi[c][j][4 + kq] = h;
    g_wk_lo[c][j][4 + kq] = l;
    a = __ldg((const float4*)(Wv + j * 128 + kc) + kq);
    b = __ldg((const float4*)(Wv + j * 128 + kc) + kq + 4);
    split4(a, h, l);
    g_wv_hi[c][j][kq] = h;
    split4(b, h, l);
    g_wv_hi[c][j][4 + kq] = h;
}

template <int PASSES>
__device__ __forceinline__ void dma_chunk(uint32_t sb, int chunk, int buf,
                                          const float* __restrict__ X,
                                          size_t base, int tid) {
    #pragma unroll
    for (int s = 0; s < 2; s++) {
        int seg = tid + s * 256;
        int row = seg >> 2, s16 = seg & 3;
        const float* hsrc =
            (const float*)(PASSES == 3 ? g_wk_hi[chunk][row] : g_wv_hi[chunk][row]);
        cp16(sb + O_AH + buf * 10240 + row * PBY + s16 * 16, hsrc + s16 * 4);
        if (PASSES == 3)
            cp16(sb + O_ALO + buf * 10240 + row * PBY + s16 * 16,
                 (const float*)g_wk_lo[chunk][row] + s16 * 4);
    }
    #pragma unroll
    for (int s = 0; s < 2; s++) {
        int seg = tid + s * 256;
        int row = seg >> 4, c16 = seg & 15;
        cp16(sb + O_RAW + buf * 8192 + row * 256 + c16 * 16,
             X + base + (size_t)(chunk * 32 + row) * 16384 + c16 * 4);
    }
}

// 128x64x128 GEMM. PASSES=3: bf16 split hh+hl+lh with fragment reuse.
// PROLOGUE: issue chunk-0 DMA here. PRE2: chunks 0 AND 1 were pre-issued
// by the caller (skip the ch==0 issue, wait counts unchanged).
template <int PASSES, bool PROLOGUE, bool PRE2>
__device__ __forceinline__ void run_gemm(
    const float* __restrict__ X, size_t base, char* sm, uint32_t sb, int tid,
    int m0, int n0, uint32_t aLane, uint32_t bLane, float acc[2][4][4],
    float* sqp, float* Sp) {
    float* smf = (float*)sm;
    const int nb = tid & 63, cg = tid >> 6;

    if (PROLOGUE) {
        dma_chunk<PASSES>(sb, 0, 0, X, base, tid);
        CP_COMMIT();
    }
    #pragma unroll 1
    for (int ch = 0; ch < 4; ch++) {
        const int b = ch & 1;
        if (ch < 3) {
            if (!(PRE2 && ch == 0)) {
                dma_chunk<PASSES>(sb, ch + 1, b ^ 1, X, base, tid);
                CP_COMMIT();
            }
            CP_WAIT(1);
        } else {
            CP_WAIT(0);
        }
        __syncthreads();  // chunk data visible; prev mma done with BH/BL

        // ---- convert B (raw f32 -> bf16 hi/lo), plus sq/S partials ----
        const float* raw = (const float*)(sm + O_RAW + b * 8192);
        float xv[8];
        #pragma unroll
        for (int cc = 0; cc < 8; cc++) xv[cc] = raw[(cg * 8 + cc) * 64 + nb];
        if (sqp) {
            #pragma unroll
            for (int cc = 0; cc < 8; cc++) {
                *sqp = fmaf(smf[O_WQ / 4 + ch * 32 + cg * 8 + cc], xv[cc], *sqp);
                *Sp = fmaf(smf[O_WK / 4 + ch * 32 + cg * 8 + cc], xv[cc], *Sp);
            }
        }
        {
            uint4 h;
            h.x = bf16pair(xv[0], xv[1]);
            h.y = bf16pair(xv[2], xv[3]);
            h.z = bf16pair(xv[4], xv[5]);
            h.w = bf16pair(xv[6], xv[7]);
            *(uint4*)(sm + O_BH + nb * PBY + cg * 16) = h;
            if (PASSES == 3) {
                uint4 l;
                l.x = bf16pair(xv[0] - bf16rt(xv[0]), xv[1] - bf16rt(xv[1]));
                l.y = bf16pair(xv[2] - bf16rt(xv[2]), xv[3] - bf16rt(xv[3]));
                l.z = bf16pair(xv[4] - bf16rt(xv[4]), xv[5] - bf16rt(xv[5]));
                l.w = bf16pair(xv[6] - bf16rt(xv[6]), xv[7] - bf16rt(xv[7]));
                *(uint4*)(sm + O_BL + nb * PBY + cg * 16) = l;
            }
        }
        __syncthreads();

        // ---- mma with fragment reuse: Ah,Bh -> hh; +Bl -> hl; +Al -> lh ----
        #pragma unroll
        for (int kk = 0; kk < 2; kk++) {
            const uint32_t aa = sb + O_AH + b * 10240 + aLane + kk * 32;
            const uint32_t bb = sb + O_BH + bLane + kk * 32;
            uint32_t ah0[4], ah1[4], bh0[4], bh1[4];
            ldsm4(ah0, aa + m0 * PBY);
            ldsm4(ah1, aa + (m0 + 16) * PBY);
            ldsm4(bh0, bb + n0 * PBY);
            ldsm4(bh1, bb + (n0 + 16) * PBY);
            mma8x(acc, ah0, ah1, bh0, bh1);
            if (PASSES == 3) {
                const uint32_t bbl = sb + O_BL + bLane + kk * 32;
                uint32_t bl0[4], bl1[4];
                ldsm4(bl0, bbl + n0 * PBY);
                ldsm4(bl1, bbl + (n0 + 16) * PBY);
                mma8x(acc, ah0, ah1, bl0, bl1);  // Ah x Bl
                const uint32_t aal = sb + O_ALO + b * 10240 + aLane + kk * 32;
                uint32_t al0[4], al1[4];
                ldsm4(al0, aal + m0 * PBY);
                ldsm4(al1, aal + (m0 + 16) * PBY);
                mma8x(acc, al0, al1, bh0, bh1);  // Al x Bh
            }
        }
    }
}

__global__ void __launch_bounds__(256, 2)
csa_kernel(const float* __restrict__ feat, const float* __restrict__ pos,
           const float* __restrict__ Wq, const float* __restrict__ Wk,
           const float* __restrict__ Wv, float* __restrict__ out) {
    extern __shared__ char sm[];
    float* smf = (float*)sm;
    const uint32_t sb = smem_u32(sm);
    const int tid = threadIdx.x;
    const int lane = tid & 31;
    const int wid = tid >> 5;
    const int m0 = (wid >> 1) * 32;
    const int n0 = (wid & 1) * 32;
    const int mg = wid >> 1;
    const float NEG = __int_as_float(0xff800000);
    const float POS = __int_as_float(0x7f800000);
    const int R = O_RED / 4;

    // column sums of Wq (tid<128) and Wk (tid>=128), fp32
    {
        const float* W = (tid < 128) ? Wq : Wk;
        const int c = tid & 127;
        float s0 = 0.f, s1 = 0.f, s2 = 0.f, s3 = 0.f;
        #pragma unroll 4
        for (int o = 0; o < 128; o += 4) {
            s0 += __ldg(W + (o + 0) * 128 + c);
            s1 += __ldg(W + (o + 1) * 128 + c);
            s2 += __ldg(W + (o + 2) * 128 + c);
            s3 += __ldg(W + (o + 3) * 128 + c);
        }
        smf[(tid < 128 ? O_WQ / 4 : O_WK / 4 - 128) + tid] = (s0 + s1) + (s2 + s3);
    }
    __syncthreads();

    const size_t base =
        (size_t)blockIdx.y * (128u * 16384u) + (size_t)blockIdx.x * 64u;
    const uint32_t aLane = (uint32_t)((lane & 15) * PBY + (lane >> 4) * 16);
    const uint32_t bLane =
        (uint32_t)(((((lane >> 4) << 3) + (lane & 7)) * PBY) + (((lane >> 3) & 1) << 4));

    // eK holds K during GEMM1, then exp(e) through GEMM2 until apply.
    float eK[2][4][4];
    #pragma unroll
    for (int a = 0; a < 2; a++)
        #pragma unroll
        for (int b = 0; b < 4; b++)
            #pragma unroll
            for (int c = 0; c < 4; c++) eK[a][b][c] = 0.f;

    // ---------------- GEMM 1: K = Wk * pos (3-pass split) ----------------
    float sqp = 0.f, Sp = 0.f;
    run_gemm<3, true, false>(pos, base, sm, sb, tid, m0, n0, aLane, bLane, eK,
                             &sqp, &Sp);

    // GEMM2 chunk-0 DMA flies during the epilogue (buf0 free).
    dma_chunk<1>(sb, 0, 0, feat, base, tid);
    CP_COMMIT();

    // ---------------- register-resident softmax epilogue ----------------
    float pmx[8], pmn[8];
    #pragma unroll
    for (int nt = 0; nt < 4; nt++)
        #pragma unroll
        for (int h = 0; h < 2; h++) {
            float v0 = eK[0][nt][h], v1 = eK[0][nt][2 + h];
            float v2 = eK[1][nt][h], v3 = eK[1][nt][2 + h];
            pmx[nt * 2 + h] = fmaxf(fmaxf(v0, v1), fmaxf(v2, v3));
            pmn[nt * 2 + h] = fminf(fminf(v0, v1), fminf(v2, v3));
        }
    #pragma unroll
    for (int i = 0; i < 8; i++) {
        #pragma unroll
        for (int d = 4; d <= 16; d <<= 1) {
            pmx[i] = fmaxf(pmx[i], __shfl_xor_sync(0xffffffffu, pmx[i], d));
            pmn[i] = fminf(pmn[i], __shfl_xor_sync(0xffffffffu, pmn[i], d));
        }
    }
    smf[R + tid] = sqp;
    smf[R + 256 + tid] = Sp;
    if (lane < 4) {
        #pragma unroll
        for (int nt = 0; nt < 4; nt++)
            #pragma unroll
            for (int h = 0; h < 2; h++) {
                int col = n0 + nt * 8 + 2 * lane + h;
                smf[R + 512 + mg * 64 + col] = pmx[nt * 2 + h];
                smf[R + 768 + mg * 64 + col] = pmn[nt * 2 + h];
            }
    }
    __syncthreads();

    // GEMM2 chunk-1 DMA: buf1 is provably free after this barrier
    // (all threads finished GEMM1 ch=3 mma/convert before reaching it).
    dma_chunk<1>(sb, 1, 1, feat, base, tid);
    CP_COMMIT();

    if (tid < 64) {
        float sq = 0.f, S = 0.f, mx = NEG, mn = POS;
        #pragma unroll
        for (int g = 0; g < 4; g++) {
            sq += smf[R + g * 64 + tid];
            S += smf[R + 256 + g * 64 + tid];
            mx = fmaxf(mx, smf[R + 512 + g * 64 + tid]);
            mn = fminf(mn, smf[R + 768 + g * 64 + tid]);
        }
        float al = sq / (1e-9f + sq * S);
        smf[O_AL / 4 + tid] = al;
        smf[O_M / 4 + tid] = fmaxf(al * mx, al * mn);
    }
    __syncthreads();
    // exp in-place in eK (stays in registers through GEMM2); denominators
    float pd[8];
    #pragma unroll
    for (int i = 0; i < 8; i++) pd[i] = 0.f;
    #pragma unroll
    for (int nt = 0; nt < 4; nt++)
        #pragma unroll
        for (int h = 0; h < 2; h++) {
            int col = n0 + nt * 8 + 2 * (lane & 3) + h;
            float al = smf[O_AL / 4 + col], mv = smf[O_M / 4 + col];
            #pragma unroll
            for (int mt = 0; mt < 2; mt++)
                #pragma unroll
                for (int half = 0; half < 2; half++) {
                    float e = __expf(fmaf(al, eK[mt][nt][2 * half + h], -mv));
                    eK[mt][nt][2 * half + h] = e;
                    pd[nt * 2 + h] += e;
                }
        }
    #pragma unroll
    for (int i = 0; i < 8; i++)
        #pragma unroll
        for (int d = 4; d <= 16; d <<= 1)
            pd[i] += __shfl_xor_sync(0xffffffffu, pd[i], d);
    if (lane < 4) {
        #pragma unroll
        for (int nt = 0; nt < 4; nt++)
            #pragma unroll
            for (int h = 0; h < 2; h++)
                smf[R + 512 + mg * 64 + n0 + nt * 8 + 2 * lane + h] =
                    pd[nt * 2 + h];
    }
    __syncthreads();
    if (tid < 64) {
        float d = 0.f;
        #pragma unroll
        for (int g = 0; g < 4; g++) d += smf[R + 512 + g * 64 + tid];
        smf[O_INV / 4 + tid] = 1.0f / d;
    }
    // (GEMM2's first in-loop sync orders s_inv before apply readers)

    // ---------------- GEMM 2: V = Wv * feat (1-pass hi) ----------------
    float accV[2][4][4];
    #pragma unroll
    for (int a = 0; a < 2; a++)
        #pragma unroll
        for (int b = 0; b < 4; b++)
            #pragma unroll
            for (int c = 0; c < 4; c++) accV[a][b][c] = 0.f;
    run_gemm<1, false, true>(feat, base, sm, sb, tid, m0, n0, aLane, bLane,
                             accV, nullptr, nullptr);

    // ---------------- apply: out = (e*inv)*V + feat (e from registers) ----
    const float* s_inv = smf + O_INV / 4;
    #pragma unroll
    for (int mt = 0; mt < 2; mt++)
        #pragma unroll
        for (int nt = 0; nt < 4; nt++) {
            int rr = m0 + mt * 16 + (lane >> 2);
            int col = n0 + nt * 8 + 2 * (lane & 3);
            float2 inv2 = *(const float2*)(s_inv + col);
            #pragma unroll
            for (int half = 0; half < 2; half++) {
                int r = rr + half * 8;
                float2 f2 =
                    __ldg((const float2*)(feat + base + (size_t)r * 16384 + col));
                float2 o;
                o.x = fmaf(eK[mt][nt][2 * half] * inv2.x,
                           accV[mt][nt][2 * half], f2.x);
                o.y = fmaf(eK[mt][nt][2 * half + 1] * inv2.y,
                           accV[mt][nt][2 * half + 1], f2.y);
                *(float2*)(out + base + (size_t)r * 16384 + col) = o;
            }
        }
}

extern "C" void kernel_launch(void* const* d_in, const int* in_sizes, int n_in,
                              void* d_out, int out_size) {
    const float* feat = (const float*)d_in[0];
    const float* pos  = (const float*)d_in[1];
    const float* Wq   = (const float*)d_in[2];
    const float* Wk   = (const float*)d_in[3];
    const float* Wv   = (const float*)d_in[4];
    float* out = (float*)d_out;

    prep_kernel<<<4, 512>>>(Wk, Wv);
    cudaFuncSetAttribute(csa_kernel, cudaFuncAttributeMaxDynamicSharedMemorySize,
                         SMEM_BYTES);
    dim3 grid(16384 / 64, 16);
    csa_kernel<<<grid, 256, SMEM_BYTES>>>(feat, pos, Wq, Wk, Wv, out);
}

// round 16
// speedup vs baseline: 1.4666x; 1.4666x over previous
#include <cuda_runtime.h>
#include <cuda_bf16.h>
#include <cstdint>

#define PBY 80      // staged row pitch bytes (40 bf16)
#define SEW 36      // sE pitch in uint32 words (72 bf16)

// smem offsets (bytes)
#define O_WQ 0            // 128 f
#define O_WK 512          // 128 f
#define O_AL 1024         // 64 f
#define O_M 1280          // 64 f
#define O_INV 1536        // 64 f
#define O_RED 1792        // 1024 f = 4096 B -> 5888
#define O_AH 6144         // 2 x 128x80 = 20480
#define O_ALO 26624       // 2 x 10240
#define O_BH 47104        // 64 x 80 = 5120
#define O_BL 52224        // 5120
#define O_RAW 57344       // 2 x 8192 raw f32 B chunks
#define O_SE 73728        // 128 x 144 B (bf16, pitch 36 words) = 18432
#define SMEM_BYTES 92160  // x2 CTAs = 184320 <= 228KB/SM

// Pre-split weights (bf16 hi/lo) in the exact smem row image (cp.async-able).
__device__ __align__(16) uint2 g_wk_hi[4][128][8];
__device__ __align__(16) uint2 g_wk_lo[4][128][8];
__device__ __align__(16) uint2 g_wv_hi[4][128][8];

__device__ __forceinline__ uint32_t smem_u32(const void* p) {
    uint32_t a;
    asm("{ .reg .u64 t; cvta.to.shared.u64 t, %1; cvt.u32.u64 %0, t; }"
        : "=r"(a) : "l"(p));
    return a;
}
__device__ __forceinline__ float bf16rt(float x) {
    return __bfloat162float(__float2bfloat16(x));
}
__device__ __forceinline__ uint32_t bf16pair(float lo, float hi) {
    __nv_bfloat162 t = __floats2bfloat162_rn(lo, hi);
    return *(uint32_t*)&t;
}
__device__ __forceinline__ void split4(float4 v, uint2& h, uint2& l) {
    h.x = bf16pair(v.x, v.y);
    h.y = bf16pair(v.z, v.w);
    l.x = bf16pair(v.x - bf16rt(v.x), v.y - bf16rt(v.y));
    l.y = bf16pair(v.z - bf16rt(v.z), v.w - bf16rt(v.w));
}
__device__ __forceinline__ void ldsm4(uint32_t* r, uint32_t addr) {
    asm volatile("ldmatrix.sync.aligned.m8n8.x4.shared.b16 {%0,%1,%2,%3}, [%4];"
                 : "=r"(r[0]), "=r"(r[1]), "=r"(r[2]), "=r"(r[3]) : "r"(addr));
}
__device__ __forceinline__ void mma16(float* d, const uint32_t* a, const uint32_t* b) {
    asm volatile(
        "mma.sync.aligned.m16n8k16.row.col.f32.bf16.bf16.f32 "
        "{%0,%1,%2,%3}, {%4,%5,%6,%7}, {%8,%9}, {%0,%1,%2,%3};"
        : "+f"(d[0]), "+f"(d[1]), "+f"(d[2]), "+f"(d[3])
        : "r"(a[0]), "r"(a[1]), "r"(a[2]), "r"(a[3]), "r"(b[0]), "r"(b[1]));
}
__device__ __forceinline__ void mma8x(float acc[2][4][4], const uint32_t* a0,
                                      const uint32_t* a1, const uint32_t* b0,
                                      const uint32_t* b1) {
    mma16(acc[0][0], a0, b0);
    mma16(acc[0][1], a0, b0 + 2);
    mma16(acc[0][2], a0, b1);
    mma16(acc[0][3], a0, b1 + 2);
    mma16(acc[1][0], a1, b0);
    mma16(acc[1][1], a1, b0 + 2);
    mma16(acc[1][2], a1, b1);
    mma16(acc[1][3], a1, b1 + 2);
}
__device__ __forceinline__ void cp16(uint32_t dst, const float* src) {
    asm volatile("cp.async.cg.shared.global [%0], [%1], 16;"
                 :: "r"(dst), "l"(__cvta_generic_to_global(src)) : "memory");
}
#define CP_COMMIT() asm volatile("cp.async.commit_group;" ::: "memory")
#define CP_WAIT(n) asm volatile("cp.async.wait_group %0;" :: "n"(n) : "memory")

// ---------------- prep: split Wk (hi+lo) and Wv (hi) once ----------------
__global__ void prep_kernel(const float* __restrict__ Wk,
                            const float* __restrict__ Wv) {
    const int c = blockIdx.x;
    const int j = threadIdx.x >> 2, kq = threadIdx.x & 3;
    const int kc = c * 32;
    uint2 h, l;
    float4 a = __ldg((const float4*)(Wk + j * 128 + kc) + kq);
    float4 b = __ldg((const float4*)(Wk + j * 128 + kc) + kq + 4);
    split4(a, h, l);
    g_wk_hi[c][j][kq] = h;
    g_wk_lo[c][j][kq] = l;
    split4(b, h, l);
    g_wk_hi[c][j][4 + kq] = h;
    g_wk_lo[c][j][4 + kq] = l;
    a = __ldg((const float4*)(Wv + j * 128 + kc) + kq);
    b = __ldg((const float4*)(Wv + j * 128 + kc) + kq + 4);
    split4(a, h, l);
    g_wv_hi[c][j][kq] = h;
    split4(b, h, l);
    g_wv_hi[c][j][4 + kq] = h;
}

template <int PASSES>
__device__ __forceinline__ void dma_chunk(uint32_t sb, int chunk, int buf,
                                          const float* __restrict__ X,
                                          size_t base, int tid) {
    #pragma unroll
    for (int s = 0; s < 2; s++) {
        int seg = tid + s * 256;
        int row = seg >> 2, s16 = seg & 3;
        const float* hsrc =
            (const float*)(PASSES == 3 ? g_wk_hi[chunk][row] : g_wv_hi[chunk][row]);
        cp16(sb + O_AH + buf * 10240 + row * PBY + s16 * 16, hsrc + s16 * 4);
        if (PASSES == 3)
            cp16(sb + O_ALO + buf * 10240 + row * PBY + s16 * 16,
                 (const float*)g_wk_lo[chunk][row] + s16 * 4);
    }
    #pragma unroll
    for (int s = 0; s < 2; s++) {
        int seg = tid + s * 256;
        int row = seg >> 4, c16 = seg & 15;
        cp16(sb + O_RAW + buf * 8192 + row * 256 + c16 * 16,
             X + base + (size_t)(chunk * 32 + row) * 16384 + c16 * 4);
    }
}

// 128x64x128 GEMM. PASSES=3: bf16 split hh+hl+lh with fragment reuse.
// PROLOGUE: issue chunk-0 DMA here. PRE2: chunks 0 AND 1 pre-issued by caller.
template <int PASSES, bool PROLOGUE, bool PRE2>
__device__ __forceinline__ void run_gemm(
    const float* __restrict__ X, size_t base, char* sm, uint32_t sb, int tid,
    int m0, int n0, uint32_t aLane, uint32_t bLane, float acc[2][4][4],
    float* sqp, float* Sp) {
    float* smf = (float*)sm;
    const int nb = tid & 63, cg = tid >> 6;

    if (PROLOGUE) {
        dma_chunk<PASSES>(sb, 0, 0, X, base, tid);
        CP_COMMIT();
    }
    #pragma unroll 1
    for (int ch = 0; ch < 4; ch++) {
        const int b = ch & 1;
        if (ch < 3) {
            if (!(PRE2 && ch == 0)) {
                dma_chunk<PASSES>(sb, ch + 1, b ^ 1, X, base, tid);
                CP_COMMIT();
            }
            CP_WAIT(1);
        } else {
            CP_WAIT(0);
        }
        __syncthreads();  // chunk data visible; prev mma done with BH/BL

        // ---- convert B (raw f32 -> bf16 hi/lo), plus sq/S partials ----
        const float* raw = (const float*)(sm + O_RAW + b * 8192);
        float xv[8];
        #pragma unroll
        for (int cc = 0; cc < 8; cc++) xv[cc] = raw[(cg * 8 + cc) * 64 + nb];
        if (sqp) {
            #pragma unroll
            for (int cc = 0; cc < 8; cc++) {
                *sqp = fmaf(smf[O_WQ / 4 + ch * 32 + cg * 8 + cc], xv[cc], *sqp);
                *Sp = fmaf(smf[O_WK / 4 + ch * 32 + cg * 8 + cc], xv[cc], *Sp);
            }
        }
        {
            uint4 h;
            h.x = bf16pair(xv[0], xv[1]);
            h.y = bf16pair(xv[2], xv[3]);
            h.z = bf16pair(xv[4], xv[5]);
            h.w = bf16pair(xv[6], xv[7]);
            *(uint4*)(sm + O_BH + nb * PBY + cg * 16) = h;
            if (PASSES == 3) {
                uint4 l;
                l.x = bf16pair(xv[0] - bf16rt(xv[0]), xv[1] - bf16rt(xv[1]));
                l.y = bf16pair(xv[2] - bf16rt(xv[2]), xv[3] - bf16rt(xv[3]));
                l.z = bf16pair(xv[4] - bf16rt(xv[4]), xv[5] - bf16rt(xv[5]));
                l.w = bf16pair(xv[6] - bf16rt(xv[6]), xv[7] - bf16rt(xv[7]));
                *(uint4*)(sm + O_BL + nb * PBY + cg * 16) = l;
            }
        }
        __syncthreads();

        // ---- mma with fragment reuse: Ah,Bh -> hh; +Bl -> hl; +Al -> lh ----
        #pragma unroll
        for (int kk = 0; kk < 2; kk++) {
            const uint32_t aa = sb + O_AH + b * 10240 + aLane + kk * 32;
            const uint32_t bb = sb + O_BH + bLane + kk * 32;
            uint32_t ah0[4], ah1[4], bh0[4], bh1[4];
            ldsm4(ah0, aa + m0 * PBY);
            ldsm4(ah1, aa + (m0 + 16) * PBY);
            ldsm4(bh0, bb + n0 * PBY);
            ldsm4(bh1, bb + (n0 + 16) * PBY);
            mma8x(acc, ah0, ah1, bh0, bh1);
            if (PASSES == 3) {
                const uint32_t bbl = sb + O_BL + bLane + kk * 32;
                uint32_t bl0[4], bl1[4];
                ldsm4(bl0, bbl + n0 * PBY);
                ldsm4(bl1, bbl + (n0 + 16) * PBY);
                mma8x(acc, ah0, ah1, bl0, bl1);  // Ah x Bl
                const uint32_t aal = sb + O_ALO + b * 10240 + aLane + kk * 32;
                uint32_t al0[4], al1[4];
                ldsm4(al0, aal + m0 * PBY);
                ldsm4(al1, aal + (m0 + 16) * PBY);
                mma8x(acc, al0, al1, bh0, bh1);  // Al x Bh
            }
        }
    }
}

__global__ void __launch_bounds__(256, 2)
csa_kernel(const float* __restrict__ feat, const float* __restrict__ pos,
           const float* __restrict__ Wq, const float* __restrict__ Wk,
           const float* __restrict__ Wv, float* __restrict__ out) {
    extern __shared__ char sm[];
    float* smf = (float*)sm;
    const uint32_t sb = smem_u32(sm);
    const int tid = threadIdx.x;
    const int lane = tid & 31;
    const int wid = tid >> 5;
    const int m0 = (wid >> 1) * 32;
    const int n0 = (wid & 1) * 32;
    const int mg = wid >> 1;
    const float NEG = __int_as_float(0xff800000);
    const float POS = __int_as_float(0x7f800000);
    const int R = O_RED / 4;

    // column sums of Wq (tid<128) and Wk (tid>=128), fp32
    {
        const float* W = (tid < 128) ? Wq : Wk;
        const int c = tid & 127;
        float s0 = 0.f, s1 = 0.f, s2 = 0.f, s3 = 0.f;
        #pragma unroll 4
        for (int o = 0; o < 128; o += 4) {
            s0 += __ldg(W + (o + 0) * 128 + c);
            s1 += __ldg(W + (o + 1) * 128 + c);
            s2 += __ldg(W + (o + 2) * 128 + c);
            s3 += __ldg(W + (o + 3) * 128 + c);
        }
        smf[(tid < 128 ? O_WQ / 4 : O_WK / 4 - 128) + tid] = (s0 + s1) + (s2 + s3);
    }
    __syncthreads();

    const size_t base =
        (size_t)blockIdx.y * (128u * 16384u) + (size_t)blockIdx.x * 64u;
    const uint32_t aLane = (uint32_t)((lane & 15) * PBY + (lane >> 4) * 16);
    const uint32_t bLane =
        (uint32_t)(((((lane >> 4) << 3) + (lane & 7)) * PBY) + (((lane >> 3) & 1) << 4));

    float acc[2][4][4];
    #pragma unroll
    for (int a = 0; a < 2; a++)
        #pragma unroll
        for (int b = 0; b < 4; b++)
            #pragma unroll
            for (int c = 0; c < 4; c++) acc[a][b][c] = 0.f;

    // ---------------- GEMM 1: K = Wk * pos (3-pass split) ----------------
    float sqp = 0.f, Sp = 0.f;
    run_gemm<3, true, false>(pos, base, sm, sb, tid, m0, n0, aLane, bLane, acc,
                             &sqp, &Sp);

    // GEMM2 chunk-0 DMA flies during the epilogue (buf0 free).
    dma_chunk<1>(sb, 0, 0, feat, base, tid);
    CP_COMMIT();

    // ---------------- register epilogue; e -> sE as bf16 ----------------
    uint32_t* sE32 = (uint32_t*)(sm + O_SE);
    float pmx[8], pmn[8];
    #pragma unroll
    for (int nt = 0; nt < 4; nt++)
        #pragma unroll
        for (int h = 0; h < 2; h++) {
            float v0 = acc[0][nt][h], v1 = acc[0][nt][2 + h];
            float v2 = acc[1][nt][h], v3 = acc[1][nt][2 + h];
            pmx[nt * 2 + h] = fmaxf(fmaxf(v0, v1), fmaxf(v2, v3));
            pmn[nt * 2 + h] = fminf(fminf(v0, v1), fminf(v2, v3));
        }
    #pragma unroll
    for (int i = 0; i < 8; i++) {
        #pragma unroll
        for (int d = 4; d <= 16; d <<= 1) {
            pmx[i] = fmaxf(pmx[i], __shfl_xor_sync(0xffffffffu, pmx[i], d));
            pmn[i] = fminf(pmn[i], __shfl_xor_sync(0xffffffffu, pmn[i], d));
        }
    }
    smf[R + tid] = sqp;
    smf[R + 256 + tid] = Sp;
    if (lane < 4) {
        #pragma unroll
        for (int nt = 0; nt < 4; nt++)
            #pragma unroll
            for (int h = 0; h < 2; h++) {
                int col = n0 + nt * 8 + 2 * lane + h;
                smf[R + 512 + mg * 64 + col] = pmx[nt * 2 + h];
                smf[R + 768 + mg * 64 + col] = pmn[nt * 2 + h];
            }
    }
    __syncthreads();

    // GEMM2 chunk-1 DMA: buf1 provably free after this barrier.
    dma_chunk<1>(sb, 1, 1, feat, base, tid);
    CP_COMMIT();

    if (tid < 64) {
        float sq = 0.f, S = 0.f, mx = NEG, mn = POS;
        #pragma unroll
        for (int g = 0; g < 4; g++) {
            sq += smf[R + g * 64 + tid];
            S += smf[R + 256 + g * 64 + tid];
            mx = fmaxf(mx, smf[R + 512 + g * 64 + tid]);
            mn = fminf(mn, smf[R + 768 + g * 64 + tid]);
        }
        float al = sq / (1e-9f + sq * S);
        smf[O_AL / 4 + tid] = al;
        smf[O_M / 4 + tid] = fmaxf(al * mx, al * mn);
    }
    __syncthreads();
    // exp from registers; write e (bf16x2) into sE once; denominators
    float pd[8];
    #pragma unroll
    for (int i = 0; i < 8; i++) pd[i] = 0.f;
    #pragma unroll
    for (int nt = 0; nt < 4; nt++)
        #pragma unroll
        for (int h = 0; h < 2; h++) {
            int col = n0 + nt * 8 + 2 * (lane & 3) + h;
            float al = smf[O_AL / 4 + col], mv = smf[O_M / 4 + col];
            #pragma unroll
            for (int mt = 0; mt < 2; mt++)
                #pragma unroll
                for (int half = 0; half < 2; half++) {
                    float e = __expf(fmaf(al, acc[mt][nt][2 * half + h], -mv));
                    acc[mt][nt][2 * half + h] = e;
                    pd[nt * 2 + h] += e;
                }
        }
    #pragma unroll
    for (int mt = 0; mt < 2; mt++)
        #pragma unroll
        for (int nt = 0; nt < 4; nt++) {
            int r = m0 + mt * 16 + (lane >> 2);
            int cw = (n0 + nt * 8 + 2 * (lane & 3)) >> 1;
            sE32[r * SEW + cw] = bf16pair(acc[mt][nt][0], acc[mt][nt][1]);
            sE32[(r + 8) * SEW + cw] = bf16pair(acc[mt][nt][2], acc[mt][nt][3]);
        }
    #pragma unroll
    for (int i = 0; i < 8; i++)
        #pragma unroll
        for (int d = 4; d <= 16; d <<= 1)
            pd[i] += __shfl_xor_sync(0xffffffffu, pd[i], d);
    if (lane < 4) {
        #pragma unroll
        for (int nt = 0; nt < 4; nt++)
            #pragma unroll
            for (int h = 0; h < 2; h++)
                smf[R + 512 + mg * 64 + n0 + nt * 8 + 2 * lane + h] =
                    pd[nt * 2 + h];
    }
    __syncthreads();
    if (tid < 64) {
        float d = 0.f;
        #pragma unroll
        for (int g = 0; g < 4; g++) d += smf[R + 512 + g * 64 + tid];
        smf[O_INV / 4 + tid] = 1.0f / d;
    }
    // (GEMM2's first in-loop sync orders s_inv/sE before apply readers)

    // ---------------- GEMM 2: V = Wv * feat (1-pass hi) ----------------
    #pragma unroll
    for (int a = 0; a < 2; a++)
        #pragma unroll
        for (int b = 0; b < 4; b++)
            #pragma unroll
            for (int c = 0; c < 4; c++) acc[a][b][c] = 0.f;
    run_gemm<1, false, true>(feat, base, sm, sb, tid, m0, n0, aLane, bLane,
                             acc, nullptr, nullptr);

    // ---------------- apply: out = (e*inv)*V + feat ----------------
    const float* s_inv = smf + O_INV / 4;
    #pragma unroll
    for (int mt = 0; mt < 2; mt++)
        #pragma unroll
        for (int nt = 0; nt < 4; nt++) {
            int rr = m0 + mt * 16 + (lane >> 2);
            int col = n0 + nt * 8 + 2 * (lane & 3);
            float2 inv2 = *(const float2*)(s_inv + col);
            #pragma unroll
            for (int half = 0; half < 2; half++) {
                int r = rr + half * 8;
                uint32_t ep = sE32[r * SEW + (col >> 1)];
                __nv_bfloat162 eb = *(__nv_bfloat162*)&ep;
                float2 f2 =
                    __ldg((const float2*)(feat + base + (size_t)r * 16384 + col));
                float2 o;
                o.x = fmaf(__bfloat162float(eb.x) * inv2.x,
                           acc[mt][nt][2 * half], f2.x);
                o.y = fmaf(__bfloat162float(eb.y) * inv2.y,
                           acc[mt][nt][2 * half + 1], f2.y);
                *(float2*)(out + base + (size_t)r * 16384 + col) = o;
            }
        }
}

extern "C" void kernel_launch(void* const* d_in, const int* in_sizes, int n_in,
                              void* d_out, int out_size) {
    const float* feat = (const float*)d_in[0];
    const float* pos  = (const float*)d_in[1];
    const float* Wq   = (const float*)d_in[2];
    const float* Wk   = (const float*)d_in[3];
    const float* Wv   = (const float*)d_in[4];
    float* out = (float*)d_out;

    prep_kernel<<<4, 512>>>(Wk, Wv);
    cudaFuncSetAttribute(csa_kernel, cudaFuncAttributeMaxDynamicSharedMemorySize,
                         SMEM_BYTES);
    dim3 grid(16384 / 64, 16);
    csa_kernel<<<grid, 256, SMEM_BYTES>>>(feat, pos, Wq, Wk, Wv, out);
}